// round 5
// baseline (speedup 1.0000x reference)
#include <cuda_runtime.h>
#include <cstdint>

#define NB 128
#define NT 1024
#define NK 128
#define NTH 512
#define IPQ 32    // candidates (transition rows) per thread

// Shared layout:
//   [0,    1024)   float state[2][128]   (double buffer)
//   [1024, 2048)   uint8 tags[1024]
//   [2048, ...)    uint8 bp[1024][128]
#define SMEM_BYTES (2048 + NT * NK)

// Tournament over 8 candidates, first-index tie-break (left wins on equal).
#define TOUR8(G, outv, outi) do {                                              \
    const float4 sA = s4[2*(G)];                                               \
    const float4 sB = s4[2*(G)+1];                                             \
    const float c0 = sA.x + tr[8*(G)+0], c1 = sA.y + tr[8*(G)+1];              \
    const float c2 = sA.z + tr[8*(G)+2], c3 = sA.w + tr[8*(G)+3];              \
    const float c4 = sB.x + tr[8*(G)+4], c5 = sB.y + tr[8*(G)+5];              \
    const float c6 = sB.z + tr[8*(G)+6], c7 = sB.w + tr[8*(G)+7];              \
    float w01 = c0; int i01 = ibase + 8*(G) + 0;                               \
    if (c1 > w01) { w01 = c1; i01 = ibase + 8*(G) + 1; }                       \
    float w23 = c2; int i23 = ibase + 8*(G) + 2;                               \
    if (c3 > w23) { w23 = c3; i23 = ibase + 8*(G) + 3; }                       \
    float w45 = c4; int i45 = ibase + 8*(G) + 4;                               \
    if (c5 > w45) { w45 = c5; i45 = ibase + 8*(G) + 5; }                       \
    float w67 = c6; int i67 = ibase + 8*(G) + 6;                               \
    if (c7 > w67) { w67 = c7; i67 = ibase + 8*(G) + 7; }                       \
    if (w23 > w01) { w01 = w23; i01 = i23; }                                   \
    if (w67 > w45) { w45 = w67; i45 = i67; }                                   \
    if (w45 > w01) { w01 = w45; i01 = i45; }                                   \
    (outv) = w01; (outi) = i01;                                                \
} while (0)

__global__ void __launch_bounds__(NTH, 1)
crf_viterbi_kernel(const float* __restrict__ logits,
                   const int* __restrict__ lengths,
                   const float* __restrict__ trans,
                   float* __restrict__ out)
{
    const int b = blockIdx.x;
    const int tid = threadIdx.x;
    const int warp = tid >> 5;
    const int lane = tid & 31;
    const int jl = lane >> 2;           // column-within-warp (0..7)
    const int q = lane & 3;             // i-quarter (0..3)
    const int j = warp * 8 + jl;        // output tag column (0..127)
    const int ibase = q * IPQ;

    extern __shared__ unsigned char smem[];
    float* stateb = (float*)smem;                  // [2][128]
    unsigned char* tags = smem + 1024;             // [1024]
    unsigned char* bp = smem + 2048;               // [1024][128]

    const float* lg = logits + (size_t)b * NT * NK;
    int len = lengths[b];
    if (len < 1) len = 1;
    if (len > NT) len = NT;

    // This thread's 32-row slice of transition column j.
    float tr[IPQ];
#pragma unroll
    for (int i = 0; i < IPQ; i++) tr[i] = trans[(ibase + i) * NK + j];

    if (tid < NK) stateb[tid] = lg[tid];   // buffer 0 = initial state
    __syncthreads();

    int p = 0;                              // current state buffer parity
    for (int t = 1; t < len; t++) {
        // prefetch this step's emission early (LDG latency hidden by tournament)
        const float lgt = __ldg(lg + t * NK + j);

        const float4* s4 = (const float4*)(stateb + 128 * p) + q * (IPQ / 4);

        // four independent 8-wide tournaments over this thread's 32 candidates
        float g0v, g1v, g2v, g3v;
        int   g0i, g1i, g2i, g3i;
        TOUR8(0, g0v, g0i);
        TOUR8(1, g1v, g1i);
        TOUR8(2, g2v, g2i);
        TOUR8(3, g3v, g3i);
        if (g1v > g0v) { g0v = g1v; g0i = g1i; }
        if (g3v > g2v) { g2v = g3v; g2i = g3i; }
        if (g2v > g0v) { g0v = g2v; g0i = g2i; }

        // warp-local merge of the 4 i-quarters (lanes q=0..3 of this column).
        // shfl partner always holds a strictly larger i-range, so strict >
        // keeps the smaller index on ties (jnp.argmax first-index semantics).
        float ov = __shfl_down_sync(0xFFFFFFFFu, g0v, 1, 4);
        int   oa = __shfl_down_sync(0xFFFFFFFFu, g0i, 1, 4);
        if (ov > g0v) { g0v = ov; g0i = oa; }
        ov = __shfl_down_sync(0xFFFFFFFFu, g0v, 2, 4);
        oa = __shfl_down_sync(0xFFFFFFFFu, g0i, 2, 4);
        if (ov > g0v) { g0v = ov; g0i = oa; }

        if (q == 0) {
            stateb[128 * (p ^ 1) + j] = g0v + lgt;
            bp[t * NK + j] = (unsigned char)g0i;
        }
        p ^= 1;
        __syncthreads();                 // step-t writes visible; orders t+1 writes after t reads
    }

    const float* fstate = stateb + 128 * ((len - 1) & 1);

    // Backtrack (thread 0, all in shared memory).
    if (tid == 0) {
        float bv = fstate[0];
        int tag = 0;
        for (int i = 1; i < NK; i++) {
            const float s = fstate[i];
            if (s > bv) { bv = s; tag = i; }
        }
        for (int t = len - 1; t < NT; t++) tags[t] = (unsigned char)tag;
        for (int t = len - 1; t >= 1; t--) {
            tag = bp[t * NK + tag];
            tags[t - 1] = (unsigned char)tag;
        }
    }
    __syncthreads();

    // One-hot write, float4-vectorized, 512 threads.
    float4* out4 = (float4*)(out + (size_t)b * NT * NK);
    for (int idx = tid; idx < NT * (NK / 4); idx += NTH) {
        const int t = idx >> 5;            // 32 float4 groups per (b,t) row
        const int kg = idx & 31;
        const int tg = tags[t];
        float4 v;
        v.x = (tg == 4 * kg + 0) ? 1.0f : 0.0f;
        v.y = (tg == 4 * kg + 1) ? 1.0f : 0.0f;
        v.z = (tg == 4 * kg + 2) ? 1.0f : 0.0f;
        v.w = (tg == 4 * kg + 3) ? 1.0f : 0.0f;
        out4[idx] = v;
    }
}

extern "C" void kernel_launch(void* const* d_in, const int* in_sizes, int n_in,
                              void* d_out, int out_size)
{
    const float* logits = (const float*)d_in[0];   // [B,T,K] f32
    const int* lengths = (const int*)d_in[1];      // [B] i32
    const float* trans = (const float*)d_in[2];    // [K,K] f32
    float* out = (float*)d_out;                    // [B,T,K] f32

    cudaFuncSetAttribute(crf_viterbi_kernel,
                         cudaFuncAttributeMaxDynamicSharedMemorySize, SMEM_BYTES);
    crf_viterbi_kernel<<<NB, NTH, SMEM_BYTES>>>(logits, lengths, trans, out);
}

// round 7
// speedup vs baseline: 2.1160x; 2.1160x over previous
#include <cuda_runtime.h>
#include <cstdint>

#define NB 128
#define NT 1024
#define NK 128
#define NTH 512
#define IPQ 32    // candidates (transition rows) per thread

// Shared layout:
//   [0,    1024)   float state[2][128]   (double buffer, XOR-swizzled)
//   [1024, 2048)   uint8 tags[1024]
//   [2048, ...)    uint8 bp[1024][128]
#define SMEM_BYTES (2048 + NT * NK)

// State swizzle: logical float4-group (q,g) -> physical slot q*8 + (g^q).
// Bank group of slot = 4*(g^q) mod 32, distinct across q for fixed g -> the
// warp's 4 q-lanes hit 4 distinct bank groups: conflict-free LDS.128.
__device__ __forceinline__ int sphys(int i) {
    return 32 * (i >> 5) + 4 * (((i >> 2) & 7) ^ (i >> 5)) + (i & 3);
}

// Tournament over 8 candidates (logical groups 2G, 2G+1), first-index
// tie-break (left wins on equal). s4 is already offset by q*8 slots; the ^q
// picks the swizzled slot holding logical group k.
#define TOUR8(G, outv, outi) do {                                              \
    const float4 sA = s4[(2*(G)) ^ q];                                         \
    const float4 sB = s4[(2*(G)+1) ^ q];                                       \
    const float c0 = sA.x + tr[8*(G)+0], c1 = sA.y + tr[8*(G)+1];              \
    const float c2 = sA.z + tr[8*(G)+2], c3 = sA.w + tr[8*(G)+3];              \
    const float c4 = sB.x + tr[8*(G)+4], c5 = sB.y + tr[8*(G)+5];              \
    const float c6 = sB.z + tr[8*(G)+6], c7 = sB.w + tr[8*(G)+7];              \
    float w01 = c0; int i01 = ibase + 8*(G) + 0;                               \
    if (c1 > w01) { w01 = c1; i01 = ibase + 8*(G) + 1; }                       \
    float w23 = c2; int i23 = ibase + 8*(G) + 2;                               \
    if (c3 > w23) { w23 = c3; i23 = ibase + 8*(G) + 3; }                       \
    float w45 = c4; int i45 = ibase + 8*(G) + 4;                               \
    if (c5 > w45) { w45 = c5; i45 = ibase + 8*(G) + 5; }                       \
    float w67 = c6; int i67 = ibase + 8*(G) + 6;                               \
    if (c7 > w67) { w67 = c7; i67 = ibase + 8*(G) + 7; }                       \
    if (w23 > w01) { w01 = w23; i01 = i23; }                                   \
    if (w67 > w45) { w45 = w67; i45 = i67; }                                   \
    if (w45 > w01) { w01 = w45; i01 = i45; }                                   \
    (outv) = w01; (outi) = i01;                                                \
} while (0)

__global__ void __launch_bounds__(NTH, 1)
crf_viterbi_kernel(const float* __restrict__ logits,
                   const int* __restrict__ lengths,
                   const float* __restrict__ trans,
                   float* __restrict__ out)
{
    const int b = blockIdx.x;
    const int tid = threadIdx.x;
    const int warp = tid >> 5;
    const int lane = tid & 31;
    const int jl = lane >> 2;           // column-within-warp (0..7)
    const int q = lane & 3;             // i-quarter (0..3)
    const int j = warp * 8 + jl;        // output tag column (0..127)
    const int ibase = q * IPQ;

    extern __shared__ unsigned char smem[];
    float* stateb = (float*)smem;                  // [2][128] swizzled
    unsigned char* tags = smem + 1024;             // [1024]
    unsigned char* bp = smem + 2048;               // [1024][128]

    const float* lg = logits + (size_t)b * NT * NK;
    int len = lengths[b];
    if (len < 1) len = 1;
    if (len > NT) len = NT;

    // This thread's 32-row slice of transition column j.
    float tr[IPQ];
#pragma unroll
    for (int i = 0; i < IPQ; i++) tr[i] = trans[(ibase + i) * NK + j];

    const int jph = sphys(j);           // swizzled slot for this column's state
    if (tid < NK) stateb[sphys(tid)] = lg[tid];   // buffer 0 = initial state
    __syncthreads();

    int p = 0;                              // current state buffer parity
    for (int t = 1; t < len; t++) {
        // prefetch this step's emission early (LDG latency hidden by tournament)
        const float lgt = __ldg(lg + t * NK + j);

        const float4* s4 = (const float4*)(stateb + 128 * p) + q * (IPQ / 4);

        // four independent 8-wide tournaments over this thread's 32 candidates
        float g0v, g1v, g2v, g3v;
        int   g0i, g1i, g2i, g3i;
        TOUR8(0, g0v, g0i);
        TOUR8(1, g1v, g1i);
        TOUR8(2, g2v, g2i);
        TOUR8(3, g3v, g3i);
        if (g1v > g0v) { g0v = g1v; g0i = g1i; }
        if (g3v > g2v) { g2v = g3v; g2i = g3i; }
        if (g2v > g0v) { g0v = g2v; g0i = g2i; }

        // warp-local merge of the 4 i-quarters (lanes q=0..3 of this column).
        // shfl partner always holds a strictly larger i-range, so strict >
        // keeps the smaller index on ties (jnp.argmax first-index semantics).
        float ov = __shfl_down_sync(0xFFFFFFFFu, g0v, 1, 4);
        int   oa = __shfl_down_sync(0xFFFFFFFFu, g0i, 1, 4);
        if (ov > g0v) { g0v = ov; g0i = oa; }
        ov = __shfl_down_sync(0xFFFFFFFFu, g0v, 2, 4);
        oa = __shfl_down_sync(0xFFFFFFFFu, g0i, 2, 4);
        if (ov > g0v) { g0v = ov; g0i = oa; }

        if (q == 0) {
            stateb[128 * (p ^ 1) + jph] = g0v + lgt;
            bp[t * NK + j] = (unsigned char)g0i;
        }
        p ^= 1;
        __syncthreads();                 // step-t writes visible; orders t+1 writes after t reads
    }

    const float* fstate = stateb + 128 * ((len - 1) & 1);

    // Backtrack (thread 0, all in shared memory).
    if (tid == 0) {
        float bv = fstate[sphys(0)];
        int tag = 0;
        for (int i = 1; i < NK; i++) {
            const float s = fstate[sphys(i)];
            if (s > bv) { bv = s; tag = i; }
        }
        for (int t = len - 1; t < NT; t++) tags[t] = (unsigned char)tag;
        for (int t = len - 1; t >= 1; t--) {
            tag = bp[t * NK + tag];
            tags[t - 1] = (unsigned char)tag;
        }
    }
    __syncthreads();

    // One-hot write, float4-vectorized, 512 threads.
    float4* out4 = (float4*)(out + (size_t)b * NT * NK);
    for (int idx = tid; idx < NT * (NK / 4); idx += NTH) {
        const int t = idx >> 5;            // 32 float4 groups per (b,t) row
        const int kg = idx & 31;
        const int tg = tags[t];
        float4 v;
        v.x = (tg == 4 * kg + 0) ? 1.0f : 0.0f;
        v.y = (tg == 4 * kg + 1) ? 1.0f : 0.0f;
        v.z = (tg == 4 * kg + 2) ? 1.0f : 0.0f;
        v.w = (tg == 4 * kg + 3) ? 1.0f : 0.0f;
        out4[idx] = v;
    }
}

extern "C" void kernel_launch(void* const* d_in, const int* in_sizes, int n_in,
                              void* d_out, int out_size)
{
    const float* logits = (const float*)d_in[0];   // [B,T,K] f32
    const int* lengths = (const int*)d_in[1];      // [B] i32
    const float* trans = (const float*)d_in[2];    // [K,K] f32
    float* out = (float*)d_out;                    // [B,T,K] f32

    cudaFuncSetAttribute(crf_viterbi_kernel,
                         cudaFuncAttributeMaxDynamicSharedMemorySize, SMEM_BYTES);
    crf_viterbi_kernel<<<NB, NTH, SMEM_BYTES>>>(logits, lengths, trans, out);
}